// round 6
// baseline (speedup 1.0000x reference)
#include <cuda_runtime.h>

// Problem constants
#define NMAX 50000
#define EMAX 1000000
#define RNUM 8
#define BNUM 30
#define JTOT 576          // 8*64 relation cols + 64 self-loop cols
#define SCANPAD 65536
#define TM 16             // dst rows per mega-block

// ---------------- static device scratch ----------------
__device__ float g_Wcat[JTOT * 64];              // [kk][o]
__device__ float g_g[(size_t)NMAX * 64];         // ((z@Wcat+b1)*s) @ W2
__device__ int   g_deg_out[NMAX];
__device__ int   g_deg_in[SCANPAD];              // zero-padded for scan
__device__ int   g_cursor[NMAX];
__device__ int   g_rowoff[NMAX + 1];
__device__ int   g_csr[EMAX];                    // src | (etype << 17)

// ---------------- f32x2 packed-FMA helpers ----------------
typedef unsigned long long ull;
__device__ __forceinline__ ull pack2(float lo, float hi) {
    ull r; asm("mov.b64 %0,{%1,%2};" : "=l"(r) : "f"(lo), "f"(hi)); return r;
}
__device__ __forceinline__ void unpack2(ull v, float& lo, float& hi) {
    asm("mov.b64 {%0,%1},%2;" : "=f"(lo), "=f"(hi) : "l"(v));
}
__device__ __forceinline__ void ffma2(ull& d, ull a, ull b) {
    asm("fma.rn.f32x2 %0,%1,%2,%0;" : "+l"(d) : "l"(a), "l"(b));
}

// ---------------- K0: zero counters ----------------
__global__ void zero_kernel(int n) {
    int i = blockIdx.x * blockDim.x + threadIdx.x;
    if (i < SCANPAD) g_deg_in[i] = 0;
    if (i < n) { g_deg_out[i] = 0; g_cursor[i] = 0; }
}

// ---------------- K1: Wcat ----------------
__global__ void wcat_kernel(const float* __restrict__ basis,
                            const float* __restrict__ comp,
                            const float* __restrict__ loopw) {
    int idx = blockIdx.x * blockDim.x + threadIdx.x;
    if (idx >= JTOT * 64) return;
    int o = idx & 63;
    int kk = idx >> 6;
    if (kk < RNUM * 64) {
        int r = kk >> 6, i = kk & 63;
        float s = 0.f;
#pragma unroll
        for (int b = 0; b < BNUM; b++)
            s += comp[r * BNUM + b] * basis[(b * 64 + i) * 64 + o];
        g_Wcat[kk * 64 + o] = s;
    } else {
        int i = kk - RNUM * 64;
        g_Wcat[kk * 64 + o] = loopw[i * 64 + o];
    }
}

// ---------------- K2: degree counts ----------------
__global__ void deg_kernel(const int* __restrict__ ei, int e) {
    int i = blockIdx.x * blockDim.x + threadIdx.x;
    if (i < e) {
        atomicAdd(&g_deg_out[ei[i]], 1);
        atomicAdd(&g_deg_in[ei[e + i]], 1);
    }
}

// ---------------- K3: single-block scan, smem-staged for coalescing ----------------
__global__ void scan_kernel(int n) {
    __shared__ int sdata[8192];
    __shared__ int wsum[32];
    __shared__ int s_carry, s_total;
    int tid = threadIdx.x, lane = tid & 31, wid = tid >> 5;
    if (tid == 0) { s_carry = 0; g_rowoff[0] = 0; }
    __syncthreads();
    for (int base = 0; base < n; base += 8192) {
        // coalesced load (deg_in is zero-padded to SCANPAD)
#pragma unroll
        for (int j = 0; j < 8; j++)
            sdata[j * 1024 + tid] = g_deg_in[base + j * 1024 + tid];
        __syncthreads();
        int v[8];
#pragma unroll
        for (int j = 0; j < 8; j++) v[j] = sdata[tid * 8 + j];
        int tsum = 0;
#pragma unroll
        for (int j = 0; j < 8; j++) tsum += v[j];
        int sc = tsum;
#pragma unroll
        for (int off = 1; off < 32; off <<= 1) {
            int t = __shfl_up_sync(0xFFFFFFFFu, sc, off);
            if (lane >= off) sc += t;
        }
        if (lane == 31) wsum[wid] = sc;
        __syncthreads();
        if (wid == 0) {
            int w = wsum[lane];
            int s2 = w;
#pragma unroll
            for (int off = 1; off < 32; off <<= 1) {
                int t = __shfl_up_sync(0xFFFFFFFFu, s2, off);
                if (lane >= off) s2 += t;
            }
            wsum[lane] = s2 - w;
            if (lane == 31) s_total = s2;
        }
        __syncthreads();
        int run = sc - tsum + wsum[wid] + s_carry;
#pragma unroll
        for (int j = 0; j < 8; j++) { run += v[j]; sdata[tid * 8 + j] = run; }
        __syncthreads();
        // coalesced store
#pragma unroll
        for (int j = 0; j < 8; j++) {
            int i = base + j * 1024 + tid;
            if (i < n) g_rowoff[i + 1] = sdata[j * 1024 + tid];
        }
        __syncthreads();
        if (tid == 0) s_carry += s_total;
        __syncthreads();
    }
}

// ---------------- K4: fill CSR ----------------
__global__ void fill_kernel(const int* __restrict__ ei,
                            const int* __restrict__ et, int e) {
    int i = blockIdx.x * blockDim.x + threadIdx.x;
    if (i < e) {
        int d = ei[e + i];
        int pos = g_rowoff[d] + atomicAdd(&g_cursor[d], 1);
        g_csr[pos] = ei[i] | (et[i] << 17);
    }
}

// ---------------- K5: MEGA — gather z-tile in smem, GEMM @Wcat, epilogue @W2 ----------------
__global__ __launch_bounds__(128) void mega_kernel(const float* __restrict__ x,
                                                   const float* __restrict__ w2,
                                                   const float* __restrict__ bias1,
                                                   int n) {
    __shared__ float zt[JTOT * TM];   // [k][m], pitch TM=16 (36.9 KB)
    __shared__ float shB[32 * 64];    // staged B chunk (8 KB)
    float* hs_sm = zt;                // overlay after GEMM1: [64][18]

    int tid = threadIdx.x, lane = tid & 31, w = tid >> 5;
    int base = blockIdx.x * TM;

    // ---- phase 1: gather per-(dst, relation) sums of x[src] into zt ----
    for (int i = 0; i < 4; i++) {
        int d = base + w * 4 + i;
        int m = w * 4 + i;
        float a0[RNUM] = {}, a1[RNUM] = {};
        int beg = 0, end = 0;
        if (d < n) { beg = g_rowoff[d]; end = g_rowoff[d + 1]; }
        int e = beg;
        for (; e + 1 < end; e += 2) {
            int p0 = g_csr[e], p1 = g_csr[e + 1];
            const float* s0 = &x[(size_t)(p0 & 0x1FFFF) * 64];
            const float* s1 = &x[(size_t)(p1 & 0x1FFFF) * 64];
            int r0 = p0 >> 17, r1 = p1 >> 17;
            float v00 = s0[lane], v01 = s0[lane + 32];
            float v10 = s1[lane], v11 = s1[lane + 32];
#pragma unroll
            for (int r = 0; r < RNUM; r++) {
                a0[r] += (r == r0) ? v00 : 0.f;
                a1[r] += (r == r0) ? v01 : 0.f;
                a0[r] += (r == r1) ? v10 : 0.f;
                a1[r] += (r == r1) ? v11 : 0.f;
            }
        }
        if (e < end) {
            int p0 = g_csr[e];
            const float* s0 = &x[(size_t)(p0 & 0x1FFFF) * 64];
            int r0 = p0 >> 17;
            float v00 = s0[lane], v01 = s0[lane + 32];
#pragma unroll
            for (int r = 0; r < RNUM; r++) {
                a0[r] += (r == r0) ? v00 : 0.f;
                a1[r] += (r == r0) ? v01 : 0.f;
            }
        }
#pragma unroll
        for (int r = 0; r < RNUM; r++) {
            zt[(r * 64 + lane) * TM + m]        = a0[r];
            zt[(r * 64 + lane + 32) * TM + m]   = a1[r];
        }
        zt[(512 + lane) * TM + m]      = (d < n) ? x[(size_t)d * 64 + lane]      : 0.f;
        zt[(512 + lane + 32) * TM + m] = (d < n) ? x[(size_t)d * 64 + lane + 32] : 0.f;
    }
    __syncthreads();

    // ---- GEMM1: hs[16x64] = zt[16x576] @ Wcat[576x64]  (f32x2, row pairs) ----
    int tx = tid & 15;        // 4-col group
    int ty = tid >> 4;        // row pair 0..7
    ull acc[4] = {};
    for (int c = 0; c < JTOT / 32; c++) {
        {   // stage Wcat chunk [32][64]
            int kr = tid >> 2, cc = (tid & 3) * 16;
            const float4* src = (const float4*)&g_Wcat[(size_t)(c * 32 + kr) * 64 + cc];
            float4* dst = (float4*)&shB[kr * 64 + cc];
            dst[0] = src[0]; dst[1] = src[1]; dst[2] = src[2]; dst[3] = src[3];
        }
        __syncthreads();
#pragma unroll
        for (int k = 0; k < 32; k++) {
            ull a = *(const ull*)&zt[(c * 32 + k) * TM + 2 * ty];
            float4 b = *(const float4*)&shB[k * 64 + tx * 4];
            ffma2(acc[0], a, pack2(b.x, b.x));
            ffma2(acc[1], a, pack2(b.y, b.y));
            ffma2(acc[2], a, pack2(b.z, b.z));
            ffma2(acc[3], a, pack2(b.w, b.w));
        }
        __syncthreads();
    }

    // ---- epilogue 1: bias1 + rsqrt(deg_out), stash hs into overlay [o][m] pitch 18 ----
    int m0 = base + 2 * ty, m1 = m0 + 1;
    float s0 = rsqrtf((float)max((m0 < n) ? g_deg_out[m0] : 1, 1));
    float s1 = rsqrtf((float)max((m1 < n) ? g_deg_out[m1] : 1, 1));
#pragma unroll
    for (int j = 0; j < 4; j++) {
        float lo, hi;
        unpack2(acc[j], lo, hi);
        float b1v = bias1[tx * 4 + j];
        hs_sm[(tx * 4 + j) * 18 + 2 * ty]     = (lo + b1v) * s0;
        hs_sm[(tx * 4 + j) * 18 + 2 * ty + 1] = (hi + b1v) * s1;
    }
    __syncthreads();

    // ---- GEMM2: g[16x64] = hs[16x64] @ W2[64x64] ----
    ull acc2[4] = {};
    for (int c = 0; c < 2; c++) {
        {
            int kr = tid >> 2, cc = (tid & 3) * 16;
            const float4* src = (const float4*)&w2[(size_t)(c * 32 + kr) * 64 + cc];
            float4* dst = (float4*)&shB[kr * 64 + cc];
            dst[0] = src[0]; dst[1] = src[1]; dst[2] = src[2]; dst[3] = src[3];
        }
        __syncthreads();
#pragma unroll
        for (int k = 0; k < 32; k++) {
            ull a = *(const ull*)&hs_sm[(c * 32 + k) * 18 + 2 * ty];
            float4 b = *(const float4*)&shB[k * 64 + tx * 4];
            ffma2(acc2[0], a, pack2(b.x, b.x));
            ffma2(acc2[1], a, pack2(b.y, b.y));
            ffma2(acc2[2], a, pack2(b.z, b.z));
            ffma2(acc2[3], a, pack2(b.w, b.w));
        }
        __syncthreads();
    }
    float lo[4], hi[4];
#pragma unroll
    for (int j = 0; j < 4; j++) unpack2(acc2[j], lo[j], hi[j]);
    if (m0 < n)
        *(float4*)&g_g[(size_t)m0 * 64 + tx * 4] = make_float4(lo[0], lo[1], lo[2], lo[3]);
    if (m1 < n)
        *(float4*)&g_g[(size_t)m1 * 64 + tx * 4] = make_float4(hi[0], hi[1], hi[2], hi[3]);
}

// ---------------- K6: out = rsqrt(deg_in)*sum g[src] + bias2  (unroll 4) ----------------
__global__ void agg3_kernel(const float* __restrict__ bias2,
                            float* __restrict__ out, int n) {
    int gw   = (blockIdx.x * blockDim.x + threadIdx.x) >> 5;
    int lane = threadIdx.x & 31;
    if (gw >= n) return;
    int beg = g_rowoff[gw], end = g_rowoff[gw + 1];

    float a0 = 0.f, a1 = 0.f;
    int e = beg;
    for (; e + 3 < end; e += 4) {
        int p0 = g_csr[e]     & 0x1FFFF, p1 = g_csr[e + 1] & 0x1FFFF;
        int p2 = g_csr[e + 2] & 0x1FFFF, p3 = g_csr[e + 3] & 0x1FFFF;
        const float* h0 = &g_g[(size_t)p0 * 64];
        const float* h1 = &g_g[(size_t)p1 * 64];
        const float* h2 = &g_g[(size_t)p2 * 64];
        const float* h3 = &g_g[(size_t)p3 * 64];
        float v0 = h0[lane], v1 = h1[lane], v2 = h2[lane], v3 = h3[lane];
        float u0 = h0[lane + 32], u1 = h1[lane + 32], u2 = h2[lane + 32], u3 = h3[lane + 32];
        a0 += (v0 + v1) + (v2 + v3);
        a1 += (u0 + u1) + (u2 + u3);
    }
    for (; e < end; e++) {
        int p = g_csr[e] & 0x1FFFF;
        a0 += g_g[(size_t)p * 64 + lane];
        a1 += g_g[(size_t)p * 64 + lane + 32];
    }
    float sc = rsqrtf((float)max(end - beg, 1));
    out[(size_t)gw * 64 + lane]      = a0 * sc + bias2[lane];
    out[(size_t)gw * 64 + lane + 32] = a1 * sc + bias2[lane + 32];
}

// ---------------- launch ----------------
extern "C" void kernel_launch(void* const* d_in, const int* in_sizes, int n_in,
                              void* d_out, int out_size) {
    const float* x     = (const float*)d_in[0];
    const int*   ei    = (const int*)d_in[1];   // int32 (JAX x64 disabled)
    const int*   et    = (const int*)d_in[3];   // int32
    const float* basis = (const float*)d_in[4];
    const float* comp  = (const float*)d_in[5];
    const float* loopw = (const float*)d_in[6];
    const float* bias1 = (const float*)d_in[7];
    const float* w2    = (const float*)d_in[8];
    const float* bias2 = (const float*)d_in[9];
    float* out = (float*)d_out;

    int n = in_sizes[0] / 64;    // 50000
    int e = in_sizes[1] / 2;     // 1000000

    zero_kernel<<<SCANPAD / 256, 256>>>(n);
    wcat_kernel<<<(JTOT * 64 + 255) / 256, 256>>>(basis, comp, loopw);
    deg_kernel<<<(e + 255) / 256, 256>>>(ei, e);
    scan_kernel<<<1, 1024>>>(n);
    fill_kernel<<<(e + 255) / 256, 256>>>(ei, et, e);

    mega_kernel<<<(n + TM - 1) / TM, 128>>>(x, w2, bias1, n);
    agg3_kernel<<<(n * 32 + 255) / 256, 256>>>(bias2, out, n);
}

// round 7
// speedup vs baseline: 2.6469x; 2.6469x over previous
#include <cuda_runtime.h>

// Problem constants
#define NMAX 50000
#define EMAX 1000000
#define RNUM 8
#define BNUM 30
#define JTOT 576          // 8*64 relation cols + 64 self-loop cols
#define SCHUNK 512        // elements per scan block
#define NBLK 98           // ceil(50000/512)
#define NPAD (NBLK * SCHUNK)   // 50176, zero-padded

// ---------------- static device scratch ----------------
__device__ float g_Wcat[JTOT * 64];              // [kk][o]
__device__ float g_z[(size_t)NMAX * JTOT];       // per-dst relation sums | self x
__device__ float g_hs[(size_t)NMAX * 64];        // layer-1 out, scaled by rsqrt(deg_out)
__device__ float g_g[(size_t)NMAX * 64];         // hs @ W2
__device__ int   g_deg_out[NMAX];
__device__ int   g_deg_in[NPAD];                 // zero-padded for scan
__device__ int   g_cursor[NMAX];
__device__ int   g_rowoff[NMAX + 1];
__device__ int   g_bsum[NBLK];
__device__ int   g_boff[NBLK];
__device__ int   g_csr[EMAX];                    // src | (etype << 17)

// ---------------- f32x2 packed-FMA helpers ----------------
typedef unsigned long long ull;
__device__ __forceinline__ ull pack2(float lo, float hi) {
    ull r; asm("mov.b64 %0,{%1,%2};" : "=l"(r) : "f"(lo), "f"(hi)); return r;
}
__device__ __forceinline__ void unpack2(ull v, float& lo, float& hi) {
    asm("mov.b64 {%0,%1},%2;" : "=f"(lo), "=f"(hi) : "l"(v));
}
__device__ __forceinline__ void ffma2(ull& d, ull a, ull b) {
    asm("fma.rn.f32x2 %0,%1,%2,%0;" : "+l"(d) : "l"(a), "l"(b));
}

// ---------------- K0: zero counters ----------------
__global__ void zero_kernel(int n) {
    int i = blockIdx.x * blockDim.x + threadIdx.x;
    if (i < NPAD) g_deg_in[i] = 0;
    if (i < n) { g_deg_out[i] = 0; g_cursor[i] = 0; }
    if (i == 0) g_rowoff[0] = 0;
}

// ---------------- K1: Wcat ----------------
__global__ void wcat_kernel(const float* __restrict__ basis,
                            const float* __restrict__ comp,
                            const float* __restrict__ loopw) {
    int idx = blockIdx.x * blockDim.x + threadIdx.x;
    if (idx >= JTOT * 64) return;
    int o = idx & 63;
    int kk = idx >> 6;
    if (kk < RNUM * 64) {
        int r = kk >> 6, i = kk & 63;
        float s = 0.f;
#pragma unroll
        for (int b = 0; b < BNUM; b++)
            s += comp[r * BNUM + b] * basis[(b * 64 + i) * 64 + o];
        g_Wcat[kk * 64 + o] = s;
    } else {
        int i = kk - RNUM * 64;
        g_Wcat[kk * 64 + o] = loopw[i * 64 + o];
    }
}

// ---------------- K2: degree counts ----------------
__global__ void deg_kernel(const int* __restrict__ ei, int e) {
    int i = blockIdx.x * blockDim.x + threadIdx.x;
    if (i < e) {
        atomicAdd(&g_deg_out[ei[i]], 1);
        atomicAdd(&g_deg_in[ei[e + i]], 1);
    }
}

// ---------------- K3a: per-block sums (98 blocks x 512 elems) ----------------
__global__ void scan1_kernel() {
    __shared__ int ws[8];
    int b = blockIdx.x, tid = threadIdx.x, lane = tid & 31, wid = tid >> 5;
    int2 v = *(const int2*)&g_deg_in[b * SCHUNK + tid * 2];
    int s = v.x + v.y;
#pragma unroll
    for (int off = 16; off >= 1; off >>= 1)
        s += __shfl_down_sync(0xFFFFFFFFu, s, off);
    if (lane == 0) ws[wid] = s;
    __syncthreads();
    if (tid == 0) {
        int t = 0;
#pragma unroll
        for (int j = 0; j < 8; j++) t += ws[j];
        g_bsum[b] = t;
    }
}

// ---------------- K3b: exclusive scan of 98 block sums (1 tiny block) ----------------
__global__ void scan2_kernel() {
    __shared__ int wsum[4];
    int tid = threadIdx.x, lane = tid & 31, wid = tid >> 5;   // 128 threads
    int v = (tid < NBLK) ? g_bsum[tid] : 0;
    int sc = v;
#pragma unroll
    for (int off = 1; off < 32; off <<= 1) {
        int t = __shfl_up_sync(0xFFFFFFFFu, sc, off);
        if (lane >= off) sc += t;
    }
    if (lane == 31) wsum[wid] = sc;
    __syncthreads();
    int woff = 0;
    for (int j = 0; j < wid; j++) woff += wsum[j];
    if (tid < NBLK) g_boff[tid] = sc - v + woff;   // exclusive
}

// ---------------- K3c: per-block scan + global offset -> rowoff ----------------
__global__ void scan3_kernel(int n) {
    __shared__ int ws[8];
    __shared__ int wx[8];
    int b = blockIdx.x, tid = threadIdx.x, lane = tid & 31, wid = tid >> 5;
    int i0 = b * SCHUNK + tid * 2;
    int2 v = *(const int2*)&g_deg_in[i0];
    int ps = v.x + v.y;
    int sc = ps;
#pragma unroll
    for (int off = 1; off < 32; off <<= 1) {
        int t = __shfl_up_sync(0xFFFFFFFFu, sc, off);
        if (lane >= off) sc += t;
    }
    if (lane == 31) ws[wid] = sc;
    __syncthreads();
    if (tid == 0) {
        int run = 0;
#pragma unroll
        for (int j = 0; j < 8; j++) { wx[j] = run; run += ws[j]; }
    }
    __syncthreads();
    int excl = (sc - ps) + wx[wid] + g_boff[b];
    int r1 = excl + v.x;
    int r2 = r1 + v.y;
    if (i0 < n)     g_rowoff[i0 + 1] = r1;
    if (i0 + 1 < n) g_rowoff[i0 + 2] = r2;
}

// ---------------- K4: fill CSR ----------------
__global__ void fill_kernel(const int* __restrict__ ei,
                            const int* __restrict__ et, int e) {
    int i = blockIdx.x * blockDim.x + threadIdx.x;
    if (i < e) {
        int d = ei[e + i];
        int pos = g_rowoff[d] + atomicAdd(&g_cursor[d], 1);
        g_csr[pos] = ei[i] | (et[i] << 17);
    }
}

// ---------------- K5: aggregate raw x per (dst, relation) -> z ----------------
__global__ void aggz_kernel(const float* __restrict__ x, int n) {
    int gw   = (blockIdx.x * blockDim.x + threadIdx.x) >> 5;
    int lane = threadIdx.x & 31;
    if (gw >= n) return;
    int beg = g_rowoff[gw], end = g_rowoff[gw + 1];

    float a0[RNUM] = {}, a1[RNUM] = {};
    int e = beg;
    for (; e + 1 < end; e += 2) {
        int p0 = g_csr[e], p1 = g_csr[e + 1];
        const float* s0 = &x[(size_t)(p0 & 0x1FFFF) * 64];
        const float* s1 = &x[(size_t)(p1 & 0x1FFFF) * 64];
        int r0 = p0 >> 17, r1 = p1 >> 17;
        float v00 = s0[lane], v01 = s0[lane + 32];
        float v10 = s1[lane], v11 = s1[lane + 32];
#pragma unroll
        for (int r = 0; r < RNUM; r++) {
            a0[r] += (r == r0) ? v00 : 0.f;
            a1[r] += (r == r0) ? v01 : 0.f;
            a0[r] += (r == r1) ? v10 : 0.f;
            a1[r] += (r == r1) ? v11 : 0.f;
        }
    }
    if (e < end) {
        int p0 = g_csr[e];
        const float* s0 = &x[(size_t)(p0 & 0x1FFFF) * 64];
        int r0 = p0 >> 17;
        float v00 = s0[lane], v01 = s0[lane + 32];
#pragma unroll
        for (int r = 0; r < RNUM; r++) {
            a0[r] += (r == r0) ? v00 : 0.f;
            a1[r] += (r == r0) ? v01 : 0.f;
        }
    }
    float* zr = &g_z[(size_t)gw * JTOT];
#pragma unroll
    for (int r = 0; r < RNUM; r++) {
        zr[r * 64 + lane]      = a0[r];    // plain stores: keep z L2-resident
        zr[r * 64 + lane + 32] = a1[r];
    }
    zr[512 + lane]      = x[(size_t)gw * 64 + lane];
    zr[512 + lane + 32] = x[(size_t)gw * 64 + lane + 32];
}

// ---------------- K6: generic 128x64 GEMM with f32x2 FMA ----------------
__global__ __launch_bounds__(256) void gemm_kernel(int asel, const float* __restrict__ Bopt,
                                                   const float* __restrict__ bias,
                                                   int M, int K, int mode) {
    __shared__ float shA[32][132];   // [k][m], padded
    __shared__ float shB[32][64];
    const float* A = asel ? g_hs : g_z;
    float*       C = asel ? g_g  : g_hs;
    const float* B = Bopt ? Bopt : g_Wcat;

    int tid = threadIdx.x;
    int tx = tid & 15, ty = tid >> 4;
    int mBase = blockIdx.x * 128;
    int rowL = tid >> 1, half = tid & 1;
    int gr = mBase + rowL;

    ull acc[4][4] = {};
    for (int k0 = 0; k0 < K; k0 += 32) {
        __syncthreads();
#pragma unroll
        for (int q = 0; q < 4; q++) {
            int kk = half * 16 + q * 4;
            float4 v = make_float4(0.f, 0.f, 0.f, 0.f);
            if (gr < M) v = *(const float4*)&A[(size_t)gr * K + k0 + kk];
            shA[kk][rowL] = v.x; shA[kk + 1][rowL] = v.y;
            shA[kk + 2][rowL] = v.z; shA[kk + 3][rowL] = v.w;
        }
        {
            int f = tid * 8, kr = f >> 6, c = f & 63;
            *(float4*)&shB[kr][c]     = *(const float4*)&B[(size_t)(k0 + kr) * 64 + c];
            *(float4*)&shB[kr][c + 4] = *(const float4*)&B[(size_t)(k0 + kr) * 64 + c + 4];
        }
        __syncthreads();
#pragma unroll
        for (int k = 0; k < 32; k++) {
            float4 b = *(const float4*)&shB[k][tx * 4];
            ull bd0 = pack2(b.x, b.x), bd1 = pack2(b.y, b.y);
            ull bd2 = pack2(b.z, b.z), bd3 = pack2(b.w, b.w);
#pragma unroll
            for (int i = 0; i < 4; i++) {
                ull a = *(const ull*)&shA[k][ty * 8 + 2 * i];
                ffma2(acc[i][0], a, bd0);
                ffma2(acc[i][1], a, bd1);
                ffma2(acc[i][2], a, bd2);
                ffma2(acc[i][3], a, bd3);
            }
        }
    }
#pragma unroll
    for (int i = 0; i < 4; i++) {
        float lo[4], hi[4];
#pragma unroll
        for (int j = 0; j < 4; j++) unpack2(acc[i][j], lo[j], hi[j]);
        int g0 = mBase + ty * 8 + 2 * i, g1 = g0 + 1;
        if (g0 < M) {
            float4 o;
            if (mode) {
                float s = rsqrtf((float)max(g_deg_out[g0], 1));
                o = make_float4((lo[0] + bias[tx * 4]) * s, (lo[1] + bias[tx * 4 + 1]) * s,
                                (lo[2] + bias[tx * 4 + 2]) * s, (lo[3] + bias[tx * 4 + 3]) * s);
            } else o = make_float4(lo[0], lo[1], lo[2], lo[3]);
            *(float4*)&C[(size_t)g0 * 64 + tx * 4] = o;
        }
        if (g1 < M) {
            float4 o;
            if (mode) {
                float s = rsqrtf((float)max(g_deg_out[g1], 1));
                o = make_float4((hi[0] + bias[tx * 4]) * s, (hi[1] + bias[tx * 4 + 1]) * s,
                                (hi[2] + bias[tx * 4 + 2]) * s, (hi[3] + bias[tx * 4 + 3]) * s);
            } else o = make_float4(hi[0], hi[1], hi[2], hi[3]);
            *(float4*)&C[(size_t)g1 * 64 + tx * 4] = o;
        }
    }
}

// ---------------- K7: out = rsqrt(deg_in)*sum g[src] + bias2  (unroll 4) ----------------
__global__ void agg3_kernel(const float* __restrict__ bias2,
                            float* __restrict__ out, int n) {
    int gw   = (blockIdx.x * blockDim.x + threadIdx.x) >> 5;
    int lane = threadIdx.x & 31;
    if (gw >= n) return;
    int beg = g_rowoff[gw], end = g_rowoff[gw + 1];

    float a0 = 0.f, a1 = 0.f;
    int e = beg;
    for (; e + 3 < end; e += 4) {
        int p0 = g_csr[e]     & 0x1FFFF, p1 = g_csr[e + 1] & 0x1FFFF;
        int p2 = g_csr[e + 2] & 0x1FFFF, p3 = g_csr[e + 3] & 0x1FFFF;
        const float* h0 = &g_g[(size_t)p0 * 64];
        const float* h1 = &g_g[(size_t)p1 * 64];
        const float* h2 = &g_g[(size_t)p2 * 64];
        const float* h3 = &g_g[(size_t)p3 * 64];
        float v0 = h0[lane], v1 = h1[lane], v2 = h2[lane], v3 = h3[lane];
        float u0 = h0[lane + 32], u1 = h1[lane + 32], u2 = h2[lane + 32], u3 = h3[lane + 32];
        a0 += (v0 + v1) + (v2 + v3);
        a1 += (u0 + u1) + (u2 + u3);
    }
    for (; e < end; e++) {
        int p = g_csr[e] & 0x1FFFF;
        a0 += g_g[(size_t)p * 64 + lane];
        a1 += g_g[(size_t)p * 64 + lane + 32];
    }
    float sc = rsqrtf((float)max(end - beg, 1));
    out[(size_t)gw * 64 + lane]      = a0 * sc + bias2[lane];
    out[(size_t)gw * 64 + lane + 32] = a1 * sc + bias2[lane + 32];
}

// ---------------- launch ----------------
extern "C" void kernel_launch(void* const* d_in, const int* in_sizes, int n_in,
                              void* d_out, int out_size) {
    const float* x     = (const float*)d_in[0];
    const int*   ei    = (const int*)d_in[1];   // int32 (JAX x64 disabled)
    const int*   et    = (const int*)d_in[3];   // int32
    const float* basis = (const float*)d_in[4];
    const float* comp  = (const float*)d_in[5];
    const float* loopw = (const float*)d_in[6];
    const float* bias1 = (const float*)d_in[7];
    const float* w2    = (const float*)d_in[8];
    const float* bias2 = (const float*)d_in[9];
    float* out = (float*)d_out;

    int n = in_sizes[0] / 64;    // 50000
    int e = in_sizes[1] / 2;     // 1000000

    zero_kernel<<<(NPAD + 255) / 256, 256>>>(n);
    wcat_kernel<<<(JTOT * 64 + 255) / 256, 256>>>(basis, comp, loopw);
    deg_kernel<<<(e + 255) / 256, 256>>>(ei, e);
    scan1_kernel<<<NBLK, 256>>>();
    scan2_kernel<<<1, 128>>>();
    scan3_kernel<<<NBLK, 256>>>(n);
    fill_kernel<<<(e + 255) / 256, 256>>>(ei, et, e);

    aggz_kernel<<<(n * 32 + 255) / 256, 256>>>(x, n);

    int mb = (n + 127) / 128;
    gemm_kernel<<<mb, 256>>>(0, nullptr, bias1, n, JTOT, 1);   // hs = (z@Wcat + b1)*rsqrt(deg_out)
    gemm_kernel<<<mb, 256>>>(1, w2, nullptr, n, 64, 0);        // g  = hs @ W2

    agg3_kernel<<<(n * 32 + 255) / 256, 256>>>(bias2, out, n);
}

// round 8
// speedup vs baseline: 2.9936x; 1.1310x over previous
#include <cuda_runtime.h>

// Problem constants
#define NMAX 50000
#define EMAX 1000000
#define RNUM 8
#define BNUM 30
#define JTOT 576            // 8*64 relation cols + 64 self-loop cols
#define NSEG (NMAX * RNUM)  // 400000 (dst,relation) segments
#define SCHUNK 512
#define NBLK2 782           // ceil(400000/512)
#define NPAD2 (NBLK2 * SCHUNK)   // 400384

// ---------------- static device scratch ----------------
__device__ float g_Wcat[JTOT * 64];              // [kk][o]
__device__ float g_z[(size_t)NMAX * JTOT];       // per-dst relation sums | self x
__device__ float g_hs[(size_t)NMAX * 64];        // layer-1 out, scaled by rsqrt(deg_out)
__device__ float g_g[(size_t)NMAX * 64];         // hs @ W2
__device__ int   g_deg_out[NMAX];
__device__ int   g_deg[NPAD2];                   // per-(dst,rel) counts, zero-padded
__device__ int   g_cursor[NSEG];
__device__ int   g_rowoff[NSEG + 1];
__device__ int   g_bsum[NBLK2];
__device__ int   g_boff[NBLK2];
__device__ int   g_csr[EMAX];                    // bare src index

// ---------------- f32x2 packed-FMA helpers ----------------
typedef unsigned long long ull;
__device__ __forceinline__ ull pack2(float lo, float hi) {
    ull r; asm("mov.b64 %0,{%1,%2};" : "=l"(r) : "f"(lo), "f"(hi)); return r;
}
__device__ __forceinline__ void unpack2(ull v, float& lo, float& hi) {
    asm("mov.b64 {%0,%1},%2;" : "=f"(lo), "=f"(hi) : "l"(v));
}
__device__ __forceinline__ void ffma2(ull& d, ull a, ull b) {
    asm("fma.rn.f32x2 %0,%1,%2,%0;" : "+l"(d) : "l"(a), "l"(b));
}

// ---------------- K0: zero counters ----------------
__global__ void zero_kernel(int n) {
    int i = blockIdx.x * blockDim.x + threadIdx.x;
    if (i < NPAD2) g_deg[i] = 0;
    if (i < NSEG) g_cursor[i] = 0;
    if (i < n) g_deg_out[i] = 0;
    if (i == 0) g_rowoff[0] = 0;
}

// ---------------- K1: Wcat ----------------
__global__ void wcat_kernel(const float* __restrict__ basis,
                            const float* __restrict__ comp,
                            const float* __restrict__ loopw) {
    int idx = blockIdx.x * blockDim.x + threadIdx.x;
    if (idx >= JTOT * 64) return;
    int o = idx & 63;
    int kk = idx >> 6;
    if (kk < RNUM * 64) {
        int r = kk >> 6, i = kk & 63;
        float s = 0.f;
#pragma unroll
        for (int b = 0; b < BNUM; b++)
            s += comp[r * BNUM + b] * basis[(b * 64 + i) * 64 + o];
        g_Wcat[kk * 64 + o] = s;
    } else {
        int i = kk - RNUM * 64;
        g_Wcat[kk * 64 + o] = loopw[i * 64 + o];
    }
}

// ---------------- K2: counts per (dst,rel) segment + out-degree ----------------
__global__ void deg_kernel(const int* __restrict__ ei,
                           const int* __restrict__ et, int e) {
    int i = blockIdx.x * blockDim.x + threadIdx.x;
    if (i < e) {
        atomicAdd(&g_deg_out[ei[i]], 1);
        atomicAdd(&g_deg[ei[e + i] * RNUM + et[i]], 1);
    }
}

// ---------------- K3a: per-block sums (782 blocks x 512 elems) ----------------
__global__ void scan1_kernel() {
    __shared__ int ws[8];
    int b = blockIdx.x, tid = threadIdx.x, lane = tid & 31, wid = tid >> 5;
    int2 v = *(const int2*)&g_deg[b * SCHUNK + tid * 2];
    int s = v.x + v.y;
#pragma unroll
    for (int off = 16; off >= 1; off >>= 1)
        s += __shfl_down_sync(0xFFFFFFFFu, s, off);
    if (lane == 0) ws[wid] = s;
    __syncthreads();
    if (tid == 0) {
        int t = 0;
#pragma unroll
        for (int j = 0; j < 8; j++) t += ws[j];
        g_bsum[b] = t;
    }
}

// ---------------- K3b: exclusive scan of 782 block sums (1 block, 1024 thr) ----------------
__global__ void scan2_kernel() {
    __shared__ int wsum[32];
    int tid = threadIdx.x, lane = tid & 31, wid = tid >> 5;
    int v = (tid < NBLK2) ? g_bsum[tid] : 0;
    int sc = v;
#pragma unroll
    for (int off = 1; off < 32; off <<= 1) {
        int t = __shfl_up_sync(0xFFFFFFFFu, sc, off);
        if (lane >= off) sc += t;
    }
    if (lane == 31) wsum[wid] = sc;
    __syncthreads();
    if (wid == 0) {
        int w = wsum[lane];
        int s2 = w;
#pragma unroll
        for (int off = 1; off < 32; off <<= 1) {
            int t = __shfl_up_sync(0xFFFFFFFFu, s2, off);
            if (lane >= off) s2 += t;
        }
        wsum[lane] = s2 - w;
    }
    __syncthreads();
    if (tid < NBLK2) g_boff[tid] = sc - v + wsum[wid];
}

// ---------------- K3c: per-block scan + global offset -> rowoff ----------------
__global__ void scan3_kernel() {
    __shared__ int ws[8];
    __shared__ int wx[8];
    int b = blockIdx.x, tid = threadIdx.x, lane = tid & 31, wid = tid >> 5;
    int i0 = b * SCHUNK + tid * 2;
    int2 v = *(const int2*)&g_deg[i0];
    int ps = v.x + v.y;
    int sc = ps;
#pragma unroll
    for (int off = 1; off < 32; off <<= 1) {
        int t = __shfl_up_sync(0xFFFFFFFFu, sc, off);
        if (lane >= off) sc += t;
    }
    if (lane == 31) ws[wid] = sc;
    __syncthreads();
    if (tid == 0) {
        int run = 0;
#pragma unroll
        for (int j = 0; j < 8; j++) { wx[j] = run; run += ws[j]; }
    }
    __syncthreads();
    int excl = (sc - ps) + wx[wid] + g_boff[b];
    int r1 = excl + v.x;
    int r2 = r1 + v.y;
    if (i0 < NSEG)     g_rowoff[i0 + 1] = r1;
    if (i0 + 1 < NSEG) g_rowoff[i0 + 2] = r2;
}

// ---------------- K4: fill CSR (sorted by (dst, rel)) ----------------
__global__ void fill_kernel(const int* __restrict__ ei,
                            const int* __restrict__ et, int e) {
    int i = blockIdx.x * blockDim.x + threadIdx.x;
    if (i < e) {
        int seg = ei[e + i] * RNUM + et[i];
        int pos = g_rowoff[seg] + atomicAdd(&g_cursor[seg], 1);
        g_csr[pos] = ei[i];
    }
}

// ---------------- K5: aggregate x[src] per (dst,rel) segment -> z ----------------
__global__ void aggz_kernel(const float* __restrict__ x, int n) {
    int gw   = (blockIdx.x * blockDim.x + threadIdx.x) >> 5;
    int lane = threadIdx.x & 31;
    if (gw >= n) return;
    float* zr = &g_z[(size_t)gw * JTOT];
    int base = gw * RNUM;
    int beg = g_rowoff[base];
#pragma unroll 1
    for (int r = 0; r < RNUM; r++) {
        int end = g_rowoff[base + r + 1];
        float a0 = 0.f, a1 = 0.f;
        int e = beg;
        for (; e + 1 < end; e += 2) {
            int p0 = g_csr[e], p1 = g_csr[e + 1];
            const float* s0 = &x[(size_t)p0 * 64];
            const float* s1 = &x[(size_t)p1 * 64];
            float v00 = s0[lane],      v10 = s1[lane];
            float v01 = s0[lane + 32], v11 = s1[lane + 32];
            a0 += v00 + v10;
            a1 += v01 + v11;
        }
        if (e < end) {
            const float* s0 = &x[(size_t)g_csr[e] * 64];
            a0 += s0[lane];
            a1 += s0[lane + 32];
        }
        zr[r * 64 + lane]      = a0;
        zr[r * 64 + lane + 32] = a1;
        beg = end;
    }
    zr[512 + lane]      = x[(size_t)gw * 64 + lane];
    zr[512 + lane + 32] = x[(size_t)gw * 64 + lane + 32];
}

// ---------------- K6: generic 128x64 GEMM with f32x2 FMA ----------------
__global__ __launch_bounds__(256) void gemm_kernel(int asel, const float* __restrict__ Bopt,
                                                   const float* __restrict__ bias,
                                                   int M, int K, int mode) {
    __shared__ float shA[32][132];   // [k][m], padded
    __shared__ float shB[32][64];
    const float* A = asel ? g_hs : g_z;
    float*       C = asel ? g_g  : g_hs;
    const float* B = Bopt ? Bopt : g_Wcat;

    int tid = threadIdx.x;
    int tx = tid & 15, ty = tid >> 4;
    int mBase = blockIdx.x * 128;
    int rowL = tid >> 1, half = tid & 1;
    int gr = mBase + rowL;

    ull acc[4][4] = {};
    for (int k0 = 0; k0 < K; k0 += 32) {
        __syncthreads();
#pragma unroll
        for (int q = 0; q < 4; q++) {
            int kk = half * 16 + q * 4;
            float4 v = make_float4(0.f, 0.f, 0.f, 0.f);
            if (gr < M) v = *(const float4*)&A[(size_t)gr * K + k0 + kk];
            shA[kk][rowL] = v.x; shA[kk + 1][rowL] = v.y;
            shA[kk + 2][rowL] = v.z; shA[kk + 3][rowL] = v.w;
        }
        {
            int f = tid * 8, kr = f >> 6, c = f & 63;
            *(float4*)&shB[kr][c]     = *(const float4*)&B[(size_t)(k0 + kr) * 64 + c];
            *(float4*)&shB[kr][c + 4] = *(const float4*)&B[(size_t)(k0 + kr) * 64 + c + 4];
        }
        __syncthreads();
#pragma unroll
        for (int k = 0; k < 32; k++) {
            float4 b = *(const float4*)&shB[k][tx * 4];
            ull bd0 = pack2(b.x, b.x), bd1 = pack2(b.y, b.y);
            ull bd2 = pack2(b.z, b.z), bd3 = pack2(b.w, b.w);
#pragma unroll
            for (int i = 0; i < 4; i++) {
                ull a = *(const ull*)&shA[k][ty * 8 + 2 * i];
                ffma2(acc[i][0], a, bd0);
                ffma2(acc[i][1], a, bd1);
                ffma2(acc[i][2], a, bd2);
                ffma2(acc[i][3], a, bd3);
            }
        }
    }
#pragma unroll
    for (int i = 0; i < 4; i++) {
        float lo[4], hi[4];
#pragma unroll
        for (int j = 0; j < 4; j++) unpack2(acc[i][j], lo[j], hi[j]);
        int g0 = mBase + ty * 8 + 2 * i, g1 = g0 + 1;
        if (g0 < M) {
            float4 o;
            if (mode) {
                float s = rsqrtf((float)max(g_deg_out[g0], 1));
                o = make_float4((lo[0] + bias[tx * 4]) * s, (lo[1] + bias[tx * 4 + 1]) * s,
                                (lo[2] + bias[tx * 4 + 2]) * s, (lo[3] + bias[tx * 4 + 3]) * s);
            } else o = make_float4(lo[0], lo[1], lo[2], lo[3]);
            *(float4*)&C[(size_t)g0 * 64 + tx * 4] = o;
        }
        if (g1 < M) {
            float4 o;
            if (mode) {
                float s = rsqrtf((float)max(g_deg_out[g1], 1));
                o = make_float4((hi[0] + bias[tx * 4]) * s, (hi[1] + bias[tx * 4 + 1]) * s,
                                (hi[2] + bias[tx * 4 + 2]) * s, (hi[3] + bias[tx * 4 + 3]) * s);
            } else o = make_float4(hi[0], hi[1], hi[2], hi[3]);
            *(float4*)&C[(size_t)g1 * 64 + tx * 4] = o;
        }
    }
}

// ---------------- K7: out = rsqrt(deg_in)*sum g[src] + bias2  (unroll 4) ----------------
__global__ void agg3_kernel(const float* __restrict__ bias2,
                            float* __restrict__ out, int n) {
    int gw   = (blockIdx.x * blockDim.x + threadIdx.x) >> 5;
    int lane = threadIdx.x & 31;
    if (gw >= n) return;
    int beg = g_rowoff[gw * RNUM], end = g_rowoff[gw * RNUM + RNUM];

    float a0 = 0.f, a1 = 0.f;
    int e = beg;
    for (; e + 3 < end; e += 4) {
        int p0 = g_csr[e], p1 = g_csr[e + 1], p2 = g_csr[e + 2], p3 = g_csr[e + 3];
        const float* h0 = &g_g[(size_t)p0 * 64];
        const float* h1 = &g_g[(size_t)p1 * 64];
        const float* h2 = &g_g[(size_t)p2 * 64];
        const float* h3 = &g_g[(size_t)p3 * 64];
        float v0 = h0[lane], v1 = h1[lane], v2 = h2[lane], v3 = h3[lane];
        float u0 = h0[lane + 32], u1 = h1[lane + 32], u2 = h2[lane + 32], u3 = h3[lane + 32];
        a0 += (v0 + v1) + (v2 + v3);
        a1 += (u0 + u1) + (u2 + u3);
    }
    for (; e < end; e++) {
        const float* h = &g_g[(size_t)g_csr[e] * 64];
        a0 += h[lane];
        a1 += h[lane + 32];
    }
    float sc = rsqrtf((float)max(end - beg, 1));
    out[(size_t)gw * 64 + lane]      = a0 * sc + bias2[lane];
    out[(size_t)gw * 64 + lane + 32] = a1 * sc + bias2[lane + 32];
}

// ---------------- launch ----------------
extern "C" void kernel_launch(void* const* d_in, const int* in_sizes, int n_in,
                              void* d_out, int out_size) {
    const float* x     = (const float*)d_in[0];
    const int*   ei    = (const int*)d_in[1];   // int32 (JAX x64 disabled)
    const int*   et    = (const int*)d_in[3];   // int32
    const float* basis = (const float*)d_in[4];
    const float* comp  = (const float*)d_in[5];
    const float* loopw = (const float*)d_in[6];
    const float* bias1 = (const float*)d_in[7];
    const float* w2    = (const float*)d_in[8];
    const float* bias2 = (const float*)d_in[9];
    float* out = (float*)d_out;

    int n = in_sizes[0] / 64;    // 50000
    int e = in_sizes[1] / 2;     // 1000000

    zero_kernel<<<(NPAD2 + 255) / 256, 256>>>(n);
    wcat_kernel<<<(JTOT * 64 + 255) / 256, 256>>>(basis, comp, loopw);
    deg_kernel<<<(e + 255) / 256, 256>>>(ei, et, e);
    scan1_kernel<<<NBLK2, 256>>>();
    scan2_kernel<<<1, 1024>>>();
    scan3_kernel<<<NBLK2, 256>>>();
    fill_kernel<<<(e + 255) / 256, 256>>>(ei, et, e);

    aggz_kernel<<<(n * 32 + 255) / 256, 256>>>(x, n);

    int mb = (n + 127) / 128;
    gemm_kernel<<<mb, 256>>>(0, nullptr, bias1, n, JTOT, 1);   // hs = (z@Wcat + b1)*rsqrt(deg_out)
    gemm_kernel<<<mb, 256>>>(1, w2, nullptr, n, 64, 0);        // g  = hs @ W2

    agg3_kernel<<<(n * 32 + 255) / 256, 256>>>(bias2, out, n);
}